// round 14
// baseline (speedup 1.0000x reference)
#include <cuda_runtime.h>
#include <cstdint>

// Problem constants (fixed by the dataset shapes)
#define HB_ 32
#define WB_ 32
#define CC_ 64
#define HA_ 512
#define WA_ 512
#define NN_ 256
#define BB_ 4
#define PATCH_ (HB_ * WB_)     // 1024
#define PLANE_ (HA_ * WA_)     // 262144

// Half-patch (16 rows) bbox: span <= sqrt(15^2+31^2)=34.5 + margins + align.
#define TWX_ 44                // tile width in floats (multiple of 4 for cp16)
#define TWY_ 39                // tile height
#define PITCHF_ 44             // word pitch (mult of 4 keeps rows 16B-aligned)
#define TILE_WORDS_ (TWY_ * PITCHF_)           // 1716
#define NSTAGE_ 2                              // channels per pipeline stage
#define NSTAGES_ (CC_ / NSTAGE_)               // 32
#define DEPTH_ 4                               // ring depth
#define LOOKAHEAD_ 3                           // stages prefetched ahead
#define BUF_WORDS_ (NSTAGE_ * TILE_WORDS_)     // 3432
#define SMEM_BYTES_ (DEPTH_ * BUF_WORDS_ * 4)  // 54912 B per block
#define NTHREADS_ 512

extern __shared__ float s_tile[];  // [DEPTH_][NSTAGE_][TILE_WORDS_]

__device__ __forceinline__ uint32_t smem_u32(const void* p) {
    uint32_t a;
    asm("{ .reg .u64 t; cvta.to.shared.u64 t, %1; cvt.u32.u64 %0, t; }"
        : "=r"(a) : "l"(p));
    return a;
}
__device__ __forceinline__ void cp_async16(uint32_t dst, const float* src) {
    asm volatile("cp.async.cg.shared.global [%0], [%1], 16;" :: "r"(dst), "l"(src));
}
__device__ __forceinline__ void cp_commit() {
    asm volatile("cp.async.commit_group;" ::: "memory");
}
// Retire all but the 2 newest groups. With ONE group committed per iteration
// (empty ones at the tail keep the count stable), committed groups at iter st
// are G0..G(st+2) with pf(j) in G_j, so this retires exactly through pf(st).
__device__ __forceinline__ void cp_wait2() {
    asm volatile("cp.async.wait_group 2;" ::: "memory");
}

__global__ __launch_bounds__(NTHREADS_, 3)
void aerial_patch_sampler_kernel(const float* __restrict__ img,
                                 const float* __restrict__ pose,
                                 float* __restrict__ out)
{
    // half folded into LOW bit: the two halves of one patch are co-scheduled
    // (shared L2 footprint), bn remains b-major overall.
    const int bx   = blockIdx.x;
    const int bn   = bx >> 1;          // b * N + n
    const int half = bx & 1;           // 0: patch rows 0-15, 1: rows 16-31
    const int b    = bn >> 8;          // N = 256

    const int wb = threadIdx.x & 31;
    const int hb = (half << 4) + (threadIdx.x >> 5);   // global patch row

    // Pose (broadcast)
    const float u  = __ldg(&pose[bn * 3 + 0]);
    const float v  = __ldg(&pose[bn * 3 + 1]);
    const float th = __ldg(&pose[bn * 3 + 2]);
    const float c = cosf(th);
    const float s = sinf(th);

    // ---- Image-space bbox of THIS HALF (ix = gu, iy = gv analytically).
    // gu0 range: half==0 -> [16,31], half==1 -> [0,15]; gv0 in [-16,15].
    const float g0 = (float)(16 * (1 - half));
    const float g1 = g0 + 15.0f;
    const float ixmin = u + fminf(c * g0, c * g1) + fminf(-16.0f * s, 15.0f * s);
    const float ixmax = u + fmaxf(c * g0, c * g1) + fmaxf(-16.0f * s, 15.0f * s);
    const float iymin = v + fminf(-s * g0, -s * g1) + fminf(-16.0f * c, 15.0f * c);
    const float iymax = v + fmaxf(-s * g0, -s * g1) + fmaxf(-16.0f * c, 15.0f * c);

    int bx0 = (int)floorf(ixmin) - 1;
    int bx1 = (int)floorf(ixmax) + 2;
    int by0 = (int)floorf(iymin) - 1;
    int by1 = (int)floorf(iymax) + 2;
    bx0 = min(max(bx0, 0), WA_ - 1) & ~3;          // 16B-aligned column base
    by0 = min(max(by0, 0), HA_ - 1);
    bx1 = min(min(max(bx1, bx0), WA_ - 1), bx0 + TWX_ - 1);
    by1 = min(min(max(by1, by0), HA_ - 1), by0 + TWY_ - 1);
    const int w4 = ((bx1 - bx0) >> 2) + 1;          // float4 per row, <= 11
    const int h  = by1 - by0 + 1;                   // rows, <= 39
    const int wf = w4 << 2;
    const int npix4 = h * w4;                       // <= 429 < 512 threads

    // ---- Per-pixel sample coords: exact fp32 round trip as the reference.
    const float gu0 = (float)(HB_ - 1 - hb);
    const float gv0 = (float)(wb - WB_ / 2);
    const float gu = u + c * gu0 + s * gv0;
    const float gv = v - s * gu0 + c * gv0;
    const float gx = (gu + 0.5f) * (2.0f / (float)WA_) - 1.0f;
    const float gy = (gv + 0.5f) * (2.0f / (float)HA_) - 1.0f;
    const bool valid = (fabsf(gx) < 1.0f) && (fabsf(gy) < 1.0f);
    const float ix = ((gx + 1.0f) * (float)WA_ - 1.0f) * 0.5f;
    const float iy = ((gy + 1.0f) * (float)HA_ - 1.0f) * 0.5f;

    const float x0f = floorf(ix);
    const float y0f = floorf(iy);
    const int x0 = (int)x0f;
    const int y0 = (int)y0f;
    const int x1 = x0 + 1;
    const int y1 = y0 + 1;

    const float wx1 = ix - x0f;
    const float wx0 = 1.0f - wx1;
    const float wy1 = iy - y0f;
    const float wy0 = 1.0f - wy1;

    const bool vx0 = valid && (x0 >= 0) && (x0 < WA_);
    const bool vx1 = valid && (x1 >= 0) && (x1 < WA_);
    const bool vy0 = valid && (y0 >= 0) && (y0 < HA_);
    const bool vy1 = valid && (y1 >= 0) && (y1 < HA_);

    const float w00 = (vx0 && vy0) ? (wx0 * wy0) : 0.0f;
    const float w10 = (vx1 && vy0) ? (wx1 * wy0) : 0.0f;
    const float w01 = (vx0 && vy1) ? (wx0 * wy1) : 0.0f;
    const float w11 = (vx1 && vy1) ? (wx1 * wy1) : 0.0f;

    // Tile-local tap indices (zero-weight taps only need to stay in-tile).
    const int sx0 = min(max(x0 - bx0, 0), wf - 1);
    const int sx1 = min(max(x1 - bx0, 0), wf - 1);
    const int sy0 = min(max(y0 - by0, 0), h - 1);
    const int sy1 = min(max(y1 - by0, 0), h - 1);
    const int i00 = sy0 * PITCHF_ + sx0;
    const int i10 = sy0 * PITCHF_ + sx1;
    const int i01 = sy1 * PITCHF_ + sx0;
    const int i11 = sy1 * PITCHF_ + sx1;

    // ---- Single 16B staging item per thread (npix4 <= 429 < 512).
    const bool sactive = (int)threadIdx.x < npix4;
    int goff = 0, soff = 0;
    if (sactive) {
        const int ry  = threadIdx.x / w4;
        const int rxq = threadIdx.x - ry * w4;
        goff = (by0 + ry) * WA_ + bx0 + (rxq << 2);   // 16B-aligned gmem offset
        soff = (ry * PITCHF_ + (rxq << 2)) * 4;       // 16B-aligned smem byte off
    }

    const float* base = img + (size_t)b * CC_ * PLANE_;
    float* op = out + (size_t)bn * CC_ * PATCH_ + hb * WB_ + wb;
    const uint32_t s_base = smem_u32(s_tile);

    #define PREFETCH(S) do {                                                  \
        if (sactive) {                                                        \
            const float* _src = base + (size_t)((S) * NSTAGE_) * PLANE_ + goff;\
            const uint32_t _dst = s_base +                                    \
                (uint32_t)(((S) % DEPTH_) * BUF_WORDS_ * 4) + (uint32_t)soff; \
            _Pragma("unroll")                                                 \
            for (int _j = 0; _j < NSTAGE_; _j++)                              \
                cp_async16(_dst + _j * (TILE_WORDS_ * 4u), _src + _j * PLANE_);\
        }                                                                     \
    } while (0)

    // Prologue: exactly one group per prefetched stage (pf0, pf1, pf2).
    PREFETCH(0); cp_commit();
    PREFETCH(1); cp_commit();
    PREFETCH(2); cp_commit();

    // Iteration st invariant: committed groups are G0..G(st+2), one per
    // prologue/iteration, with pf(j) in G_j (tail groups EMPTY but still
    // committed -> stable count). cp_wait2 retires through G_st = pf(st);
    // the barrier publishes all threads' copies and proves gather(st-1)
    // finished everywhere, so PREFETCH(st+3) into buf (st-1)%4 cannot race.
    #pragma unroll 1
    for (int st = 0; st < NSTAGES_; st++) {
        cp_wait2();                  // pf(st) complete (own copies)
        __syncthreads();             // publish pf(st); gather(st-1) done by all

        if (st + LOOKAHEAD_ < NSTAGES_) PREFETCH(st + LOOKAHEAD_);
        cp_commit();                 // ALWAYS commit: stable group count

        const float* t = s_tile + (st % DEPTH_) * BUF_WORDS_;
        #pragma unroll
        for (int j = 0; j < NSTAGE_; j++) {
            const float* tc = t + j * TILE_WORDS_;
            op[(st * NSTAGE_ + j) * PATCH_] =
                w00 * tc[i00] + w10 * tc[i10] + w01 * tc[i01] + w11 * tc[i11];
        }
    }
    #undef PREFETCH
}

extern "C" void kernel_launch(void* const* d_in, const int* in_sizes, int n_in,
                              void* d_out, int out_size)
{
    const float* aer_feat = (const float*)d_in[0];   // (B, C, 512, 512) fp32
    const float* pose_uvr = (const float*)d_in[1];   // (B, N, 3) fp32
    float* out = (float*)d_out;                      // (B, N, C, 32, 32) fp32

    static int smem_set = 0;
    if (!smem_set) {
        cudaFuncSetAttribute(aerial_patch_sampler_kernel,
                             cudaFuncAttributeMaxDynamicSharedMemorySize,
                             SMEM_BYTES_);
        smem_set = 1;
    }

    dim3 grid(BB_ * NN_ * 2);   // bn*2 + half: halves co-scheduled, b-major
    dim3 block(NTHREADS_);      // 16 warps; 3 blocks/SM = 3 barrier domains
    aerial_patch_sampler_kernel<<<grid, block, SMEM_BYTES_>>>(aer_feat, pose_uvr, out);
}

// round 16
// speedup vs baseline: 1.0530x; 1.0530x over previous
#include <cuda_runtime.h>
#include <cstdint>

// Problem constants (fixed by the dataset shapes)
#define HB_ 32
#define WB_ 32
#define CC_ 64
#define HA_ 512
#define WA_ 512
#define NN_ 256
#define BB_ 4
#define PATCH_ (HB_ * WB_)     // 1024
#define PLANE_ (HA_ * WA_)     // 262144

// Half-patch (16 rows) bbox: span <= sqrt(15^2+31^2)=34.5 + margins + align.
#define TWX_ 44                // tile width in floats (11 float4 slots)
#define TWY_ 39                // tile height
#define PITCHF_ 44             // word pitch; rows hold 11 rotated float4 blocks
#define ROWF4_ 11              // float4 slots per row (coprime with banks)
#define TILE_WORDS_ (TWY_ * PITCHF_)           // 1716
#define NSTAGE_ 2                              // channels per pipeline stage
#define NSTAGES_ (CC_ / NSTAGE_)               // 32
#define DEPTH_ 4                               // ring depth
#define LOOKAHEAD_ 3                           // stages prefetched ahead
#define BUF_WORDS_ (NSTAGE_ * TILE_WORDS_)     // 3432
#define SMEM_BYTES_ (DEPTH_ * BUF_WORDS_ * 4)  // 54912 B per block (4 blocks/SM)
#define NTHREADS_ 512

extern __shared__ float s_tile[];  // [DEPTH_][NSTAGE_][TILE_WORDS_]

__device__ __forceinline__ uint32_t smem_u32(const void* p) {
    uint32_t a;
    asm("{ .reg .u64 t; cvta.to.shared.u64 t, %1; cvt.u32.u64 %0, t; }"
        : "=r"(a) : "l"(p));
    return a;
}
__device__ __forceinline__ void cp_async16(uint32_t dst, const float* src) {
    asm volatile("cp.async.cg.shared.global [%0], [%1], 16;" :: "r"(dst), "l"(src));
}
__device__ __forceinline__ void cp_commit() {
    asm volatile("cp.async.commit_group;" ::: "memory");
}
// Retire all but the 2 newest groups. With ONE group committed per iteration
// (empty ones at the tail keep the count stable), committed groups at iter st
// are G0..G(st+2) with pf(j) in G_j, so this retires exactly through pf(st).
__device__ __forceinline__ void cp_wait2() {
    asm volatile("cp.async.wait_group 2;" ::: "memory");
}

// Row rotation: float4 slot f4 in row ry lives at slot (f4 + 3*ry) mod 11.
// Breaks the vertical bank periodicity (pitch 44 -> gcd(12,32)=4 -> 4-way)
// while keeping 16B units intact for cp.async. Static per thread: applied
// only in setup (staging dst + 4 tap indices); hot loop unchanged.
__device__ __forceinline__ int rot_word(int sy, int sx) {
    const int f4 = sx >> 2;
    const int r  = (f4 + 3 * sy) % ROWF4_;
    return sy * PITCHF_ + (r << 2) + (sx & 3);
}

__global__ __launch_bounds__(NTHREADS_, 3)
void aerial_patch_sampler_kernel(const float* __restrict__ img,
                                 const float* __restrict__ pose,
                                 float* __restrict__ out)
{
    // half folded into LOW bit: the two halves of one patch are co-scheduled
    // (shared L2 footprint), bn remains b-major overall.
    const int bx   = blockIdx.x;
    const int bn   = bx >> 1;          // b * N + n
    const int half = bx & 1;           // 0: patch rows 0-15, 1: rows 16-31
    const int b    = bn >> 8;          // N = 256

    const int wb = threadIdx.x & 31;
    const int hb = (half << 4) + (threadIdx.x >> 5);   // global patch row

    // Pose (broadcast)
    const float u  = __ldg(&pose[bn * 3 + 0]);
    const float v  = __ldg(&pose[bn * 3 + 1]);
    const float th = __ldg(&pose[bn * 3 + 2]);
    const float c = cosf(th);
    const float s = sinf(th);

    // ---- Image-space bbox of THIS HALF (ix = gu, iy = gv analytically).
    // gu0 range: half==0 -> [16,31], half==1 -> [0,15]; gv0 in [-16,15].
    const float g0 = (float)(16 * (1 - half));
    const float g1 = g0 + 15.0f;
    const float ixmin = u + fminf(c * g0, c * g1) + fminf(-16.0f * s, 15.0f * s);
    const float ixmax = u + fmaxf(c * g0, c * g1) + fmaxf(-16.0f * s, 15.0f * s);
    const float iymin = v + fminf(-s * g0, -s * g1) + fminf(-16.0f * c, 15.0f * c);
    const float iymax = v + fmaxf(-s * g0, -s * g1) + fmaxf(-16.0f * c, 15.0f * c);

    int bx0 = (int)floorf(ixmin) - 1;
    int bx1 = (int)floorf(ixmax) + 2;
    int by0 = (int)floorf(iymin) - 1;
    int by1 = (int)floorf(iymax) + 2;
    bx0 = min(max(bx0, 0), WA_ - 1) & ~3;          // 16B-aligned column base
    by0 = min(max(by0, 0), HA_ - 1);
    bx1 = min(min(max(bx1, bx0), WA_ - 1), bx0 + TWX_ - 1);
    by1 = min(min(max(by1, by0), HA_ - 1), by0 + TWY_ - 1);
    const int w4 = ((bx1 - bx0) >> 2) + 1;          // float4 per row, <= 11
    const int h  = by1 - by0 + 1;                   // rows, <= 39
    const int wf = w4 << 2;
    const int npix4 = h * w4;                       // <= 429 < 512 threads

    // ---- Per-pixel sample coords: exact fp32 round trip as the reference.
    const float gu0 = (float)(HB_ - 1 - hb);
    const float gv0 = (float)(wb - WB_ / 2);
    const float gu = u + c * gu0 + s * gv0;
    const float gv = v - s * gu0 + c * gv0;
    const float gx = (gu + 0.5f) * (2.0f / (float)WA_) - 1.0f;
    const float gy = (gv + 0.5f) * (2.0f / (float)HA_) - 1.0f;
    const bool valid = (fabsf(gx) < 1.0f) && (fabsf(gy) < 1.0f);
    const float ix = ((gx + 1.0f) * (float)WA_ - 1.0f) * 0.5f;
    const float iy = ((gy + 1.0f) * (float)HA_ - 1.0f) * 0.5f;

    const float x0f = floorf(ix);
    const float y0f = floorf(iy);
    const int x0 = (int)x0f;
    const int y0 = (int)y0f;
    const int x1 = x0 + 1;
    const int y1 = y0 + 1;

    const float wx1 = ix - x0f;
    const float wx0 = 1.0f - wx1;
    const float wy1 = iy - y0f;
    const float wy0 = 1.0f - wy1;

    const bool vx0 = valid && (x0 >= 0) && (x0 < WA_);
    const bool vx1 = valid && (x1 >= 0) && (x1 < WA_);
    const bool vy0 = valid && (y0 >= 0) && (y0 < HA_);
    const bool vy1 = valid && (y1 >= 0) && (y1 < HA_);

    const float w00 = (vx0 && vy0) ? (wx0 * wy0) : 0.0f;
    const float w10 = (vx1 && vy0) ? (wx1 * wy0) : 0.0f;
    const float w01 = (vx0 && vy1) ? (wx0 * wy1) : 0.0f;
    const float w11 = (vx1 && vy1) ? (wx1 * wy1) : 0.0f;

    // Tile-local tap indices (zero-weight taps only need to stay in-tile),
    // with the mod-11 row rotation applied (setup-only cost).
    const int sx0 = min(max(x0 - bx0, 0), wf - 1);
    const int sx1 = min(max(x1 - bx0, 0), wf - 1);
    const int sy0 = min(max(y0 - by0, 0), h - 1);
    const int sy1 = min(max(y1 - by0, 0), h - 1);
    const int i00 = rot_word(sy0, sx0);
    const int i10 = rot_word(sy0, sx1);
    const int i01 = rot_word(sy1, sx0);
    const int i11 = rot_word(sy1, sx1);

    // ---- Single 16B staging item per thread (npix4 <= 429 < 512).
    const bool sactive = (int)threadIdx.x < npix4;
    int goff = 0, soff = 0;
    if (sactive) {
        const int ry  = threadIdx.x / w4;
        const int rxq = threadIdx.x - ry * w4;          // float4 slot index
        goff = (by0 + ry) * WA_ + bx0 + (rxq << 2);     // 16B-aligned gmem off
        const int rr = (rxq + 3 * ry) % ROWF4_;         // rotated slot
        soff = (ry * PITCHF_ + (rr << 2)) * 4;          // 16B-aligned smem byte
    }

    const float* base = img + (size_t)b * CC_ * PLANE_;
    float* op = out + (size_t)bn * CC_ * PATCH_ + hb * WB_ + wb;
    const uint32_t s_base = smem_u32(s_tile);

    #define PREFETCH(S) do {                                                  \
        if (sactive) {                                                        \
            const float* _src = base + (size_t)((S) * NSTAGE_) * PLANE_ + goff;\
            const uint32_t _dst = s_base +                                    \
                (uint32_t)(((S) % DEPTH_) * BUF_WORDS_ * 4) + (uint32_t)soff; \
            _Pragma("unroll")                                                 \
            for (int _j = 0; _j < NSTAGE_; _j++)                              \
                cp_async16(_dst + _j * (TILE_WORDS_ * 4u), _src + _j * PLANE_);\
        }                                                                     \
    } while (0)

    // Prologue: exactly one group per prefetched stage (pf0, pf1, pf2).
    PREFETCH(0); cp_commit();
    PREFETCH(1); cp_commit();
    PREFETCH(2); cp_commit();

    // Iteration st invariant: committed groups are G0..G(st+2), one per
    // prologue/iteration, with pf(j) in G_j (tail groups EMPTY but still
    // committed -> stable count). cp_wait2 retires through G_st = pf(st);
    // the barrier publishes all threads' copies and proves gather(st-1)
    // finished everywhere, so PREFETCH(st+3) into buf (st-1)%4 cannot race.
    #pragma unroll 1
    for (int st = 0; st < NSTAGES_; st++) {
        cp_wait2();                  // pf(st) complete (own copies)
        __syncthreads();             // publish pf(st); gather(st-1) done by all

        if (st + LOOKAHEAD_ < NSTAGES_) PREFETCH(st + LOOKAHEAD_);
        cp_commit();                 // ALWAYS commit: stable group count

        const float* t = s_tile + (st % DEPTH_) * BUF_WORDS_;
        #pragma unroll
        for (int j = 0; j < NSTAGE_; j++) {
            const float* tc = t + j * TILE_WORDS_;
            op[(st * NSTAGE_ + j) * PATCH_] =
                w00 * tc[i00] + w10 * tc[i10] + w01 * tc[i01] + w11 * tc[i11];
        }
    }
    #undef PREFETCH
}

extern "C" void kernel_launch(void* const* d_in, const int* in_sizes, int n_in,
                              void* d_out, int out_size)
{
    const float* aer_feat = (const float*)d_in[0];   // (B, C, 512, 512) fp32
    const float* pose_uvr = (const float*)d_in[1];   // (B, N, 3) fp32
    float* out = (float*)d_out;                      // (B, N, C, 32, 32) fp32

    static int smem_set = 0;
    if (!smem_set) {
        cudaFuncSetAttribute(aerial_patch_sampler_kernel,
                             cudaFuncAttributeMaxDynamicSharedMemorySize,
                             SMEM_BYTES_);
        smem_set = 1;
    }

    dim3 grid(BB_ * NN_ * 2);   // bn*2 + half: halves co-scheduled, b-major
    dim3 block(NTHREADS_);      // 16 warps; 4 blocks/SM = 4 barrier domains
    aerial_patch_sampler_kernel<<<grid, block, SMEM_BYTES_>>>(aer_feat, pose_uvr, out);
}